// round 2
// baseline (speedup 1.0000x reference)
#include <cuda_runtime.h>
#include <math.h>

#define L_LAYERS 250
#define N_TRACES 600
#define N_THETA  30
#define NI   (L_LAYERS - 1)            // 249 interfaces (last ref row is zero)
#define NCOL (N_TRACES * N_THETA)      // 18000
#define LT   (NI * N_TRACES)           // 149400

// Scratch for rpp, layout R[k][t*N_THETA + a]
__device__ float g_R[NI * NCOL];

// ---------------------------------------------------------------------------
// Phase 1: Zoeppritz Rpp via Cramer's rule.
// One thread per (l, t); loops over the 30 angles with per-(l,t) invariants
// hoisted. sin(arcsin(clip(x))) = clip(x); cos(arcsin(clip(x))) = sqrt(1-x^2).
// ---------------------------------------------------------------------------
__global__ void zoe_phase1(const float* __restrict__ vp,
                           const float* __restrict__ vs,
                           const float* __restrict__ rho,
                           const float* __restrict__ theta) {
    __shared__ float s_sth[N_THETA], s_cth[N_THETA];
    int tid = threadIdx.x;
    if (tid < N_THETA) {
        float sv, cv;
        sincosf(theta[tid], &sv, &cv);
        s_sth[tid] = sv;
        s_cth[tid] = cv;
    }
    __syncthreads();

    int idx = blockIdx.x * blockDim.x + tid;
    if (idx >= LT) return;
    int l = idx / N_TRACES;
    int t = idx - l * N_TRACES;

    float a1 = vp[l * N_TRACES + t],  a2 = vp[(l + 1) * N_TRACES + t];
    float b1 = vs[l * N_TRACES + t],  b2 = vs[(l + 1) * N_TRACES + t];
    float r1 = rho[l * N_TRACES + t], r2 = rho[(l + 1) * N_TRACES + t];

    float inva1 = __fdividef(1.f, a1);
    float rb1 = r1 * b1, rb2 = r2 * b2;
    float ra1 = r1 * a1, ra2 = r2 * a2;

    float* outp = &g_R[l * NCOL + t * N_THETA];

#pragma unroll 5
    for (int a = 0; a < N_THETA; a++) {
        float sth = s_sth[a], cth = s_cth[a];
        float p = sth * inva1;

        float st2 = fminf(fmaxf(p * a2, -1.f), 1.f);
        float ct2 = sqrtf(fmaxf(1.f - st2 * st2, 0.f));
        float sp1 = fminf(fmaxf(p * b1, -1.f), 1.f);
        float cp1 = sqrtf(fmaxf(1.f - sp1 * sp1, 0.f));
        float sp2 = fminf(fmaxf(p * b2, -1.f), 1.f);
        float cp2 = sqrtf(fmaxf(1.f - sp2 * sp2, 0.f));

        float w1 = 1.f - 2.f * sp1 * sp1;
        float w2 = 1.f - 2.f * sp2 * sp2;

        float m00 = -sth,                  m01 = -cp1,                  m02 = st2,                   m03 = cp2;
        float m10 =  cth,                  m11 = -sp1,                  m12 = ct2,                   m13 = -sp2;
        float m20 = 2.f * rb1 * sp1 * cth, m21 = rb1 * w1,              m22 = 2.f * rb2 * sp2 * ct2, m23 = rb2 * w2;
        float m30 = -ra1 * w1,             m31 = 2.f * rb1 * sp1 * cp1, m32 = ra2 * w2,              m33 = -2.f * rb2 * sp2 * cp2;

        float n0 = sth, n1 = cth, n2 = m20, n3 = -m30;

        float P01 = m00 * m11 - m01 * m10;
        float P02 = m00 * m12 - m02 * m10;
        float P03 = m00 * m13 - m03 * m10;
        float P12 = m01 * m12 - m02 * m11;
        float P13 = m01 * m13 - m03 * m11;
        float P23 = m02 * m13 - m03 * m12;

        float Q01 = m20 * m31 - m21 * m30;
        float Q02 = m20 * m32 - m22 * m30;
        float Q03 = m20 * m33 - m23 * m30;
        float Q12 = m21 * m32 - m22 * m31;
        float Q13 = m21 * m33 - m23 * m31;
        float Q23 = m22 * m33 - m23 * m32;

        float detM = P01 * Q23 - P02 * Q13 + P03 * Q12
                   + P12 * Q03 - P13 * Q02 + P23 * Q01;

        float Pn01 = n0 * m11 - m01 * n1;
        float Pn02 = n0 * m12 - m02 * n1;
        float Pn03 = n0 * m13 - m03 * n1;
        float Qn01 = n2 * m31 - m21 * n3;
        float Qn02 = n2 * m32 - m22 * n3;
        float Qn03 = n2 * m33 - m23 * n3;

        float detM0 = Pn01 * Q23 - Pn02 * Q13 + Pn03 * Q12
                    + P12 * Qn03 - P13 * Qn02 + P23 * Qn01;

        outp[a] = __fdividef(detM0, detM);
    }
}

// ---------------------------------------------------------------------------
// Phase 2: out[t, l, a] = sum_k W[l, k] * R[k, t*30+a]
// SGEMM M=250, N=18000, K=249. 128x128x8 tiles, 256 threads, 8x8 microtile,
// double-buffered smem. Grid = 141 x 2 = 282 blocks (one wave at 2/SM).
// ---------------------------------------------------------------------------
#define BM 128
#define BN 128
#define BK 8

__global__ __launch_bounds__(256, 2)
void zoe_gemm(const float* __restrict__ W, float* __restrict__ out) {
    __shared__ float As[2][BK][BM + 4];   // padded: conflict-free STS
    __shared__ float Bs[2][BK][BN];

    int tid = threadIdx.x;
    int tx = tid & 15;        // N direction (16)
    int ty = tid >> 4;        // M direction (16)
    int bm = blockIdx.y * BM;
    int bn = blockIdx.x * BN;

    // A-tile load mapping: 128x8 = 1024 scalars, 4 per thread
    int a_k = tid & 7;        // 0..7
    int a_m = tid >> 3;       // 0..31, step +32
    // B-tile load mapping: 8x128 = 256 float4, 1 per thread
    int b_k = tid >> 5;       // 0..7
    int b_n = (tid & 31) * 4; // 0..124

    const int KTILES = (NI + BK - 1) / BK;   // 32

    float acc[8][8];
#pragma unroll
    for (int i = 0; i < 8; i++)
#pragma unroll
        for (int j = 0; j < 8; j++) acc[i][j] = 0.f;

    // ---- prologue: stage 0 ----
    {
        int k0 = 0;
#pragma unroll
        for (int i = 0; i < 4; i++) {
            int m = a_m + i * 32;
            int gm = bm + m, gk = k0 + a_k;
            float v = 0.f;
            if (gm < L_LAYERS && gk < NI) v = W[gm * L_LAYERS + gk];
            As[0][a_k][m] = v;
        }
        int gk = k0 + b_k;
        int gn = bn + b_n;
        float4 v = make_float4(0.f, 0.f, 0.f, 0.f);
        if (gk < NI && gn < NCOL) v = *(const float4*)&g_R[gk * NCOL + gn];
        *(float4*)&Bs[0][b_k][b_n] = v;
    }
    __syncthreads();

    int buf = 0;
    for (int s = 0; s < KTILES; s++) {
        // issue next stage's loads into the other buffer
        if (s + 1 < KTILES) {
            int k0 = (s + 1) * BK;
            int nb = buf ^ 1;
#pragma unroll
            for (int i = 0; i < 4; i++) {
                int m = a_m + i * 32;
                int gm = bm + m, gk = k0 + a_k;
                float v = 0.f;
                if (gm < L_LAYERS && gk < NI) v = W[gm * L_LAYERS + gk];
                As[nb][a_k][m] = v;
            }
            int gk = k0 + b_k;
            int gn = bn + b_n;
            float4 v = make_float4(0.f, 0.f, 0.f, 0.f);
            if (gk < NI && gn < NCOL) v = *(const float4*)&g_R[gk * NCOL + gn];
            *(float4*)&Bs[nb][b_k][b_n] = v;
        }

        // compute on current buffer
#pragma unroll
        for (int kk = 0; kk < BK; kk++) {
            float ar[8], br[8];
            *(float4*)&ar[0] = *(const float4*)&As[buf][kk][ty * 8];
            *(float4*)&ar[4] = *(const float4*)&As[buf][kk][ty * 8 + 4];
            *(float4*)&br[0] = *(const float4*)&Bs[buf][kk][tx * 8];
            *(float4*)&br[4] = *(const float4*)&Bs[buf][kk][tx * 8 + 4];
#pragma unroll
            for (int i = 0; i < 8; i++)
#pragma unroll
                for (int j = 0; j < 8; j++)
                    acc[i][j] = fmaf(ar[i], br[j], acc[i][j]);
        }
        __syncthreads();
        buf ^= 1;
    }

    // epilogue: out[t*7500 + l*30 + a], n = t*30 + a
#pragma unroll
    for (int i = 0; i < 8; i++) {
        int l = bm + ty * 8 + i;
        if (l >= L_LAYERS) continue;
#pragma unroll
        for (int j = 0; j < 8; j++) {
            int n = bn + tx * 8 + j;
            if (n >= NCOL) continue;
            int t = n / N_THETA;
            int a = n - t * N_THETA;
            out[t * (L_LAYERS * N_THETA) + l * N_THETA + a] = acc[i][j];
        }
    }
}

extern "C" void kernel_launch(void* const* d_in, const int* in_sizes, int n_in,
                              void* d_out, int out_size) {
    const float* vp      = (const float*)d_in[0];
    const float* vs      = (const float*)d_in[1];
    const float* rho     = (const float*)d_in[2];
    const float* theta   = (const float*)d_in[3];
    const float* wavemat = (const float*)d_in[4];
    float* out = (float*)d_out;

    zoe_phase1<<<(LT + 255) / 256, 256>>>(vp, vs, rho, theta);

    dim3 grid((NCOL + BN - 1) / BN, (L_LAYERS + BM - 1) / BM);
    zoe_gemm<<<grid, 256>>>(wavemat, out);
}

// round 3
// speedup vs baseline: 2.6537x; 2.6537x over previous
#include <cuda_runtime.h>
#include <cuda_bf16.h>
#include <math.h>
#include <stdint.h>

#define L_LAYERS 250
#define N_TRACES 600
#define N_THETA  30
#define NI   249                 // interfaces (ref row 249 is zero -> dropped)
#define NCOL 18000               // N_TRACES * N_THETA
#define NP   18048               // padded R plane pitch (cols)
#define KPAD 256                 // padded K (rows of R / cols of W)
#define TOTAL (NI * NCOL)

// bf16 hi/lo planes. __device__ globals are zero-initialized at module load;
// pad regions (rows >=249, cols >=18000) are additionally re-zeroed every
// launch by zoe_zeropad for safety.
__device__ __nv_bfloat16 g_Rhi[KPAD * NP];
__device__ __nv_bfloat16 g_Rlo[KPAD * NP];
__device__ __nv_bfloat16 g_Whi[256 * 256];
__device__ __nv_bfloat16 g_Wlo[256 * 256];

// ---------------------------------------------------------------------------
// Phase 1: Zoeppritz Rpp via Cramer's rule, one thread per (l, t, a) with
// a fastest (round-1 mapping: coalesced stores, near-broadcast loads).
// sin(arcsin(clip(x))) = clip(x); cos(arcsin(clip(x))) = sqrt(1 - clip^2).
// Writes split-bf16 planes: r = hi + lo.
// ---------------------------------------------------------------------------
__global__ void zoe_phase1(const float* __restrict__ vp,
                           const float* __restrict__ vs,
                           const float* __restrict__ rho,
                           const float* __restrict__ theta) {
    __shared__ float s_sth[N_THETA], s_cth[N_THETA];
    int tid = threadIdx.x;
    if (tid < N_THETA) {
        float sv, cv;
        sincosf(theta[tid], &sv, &cv);
        s_sth[tid] = sv;
        s_cth[tid] = cv;
    }
    __syncthreads();

    int idx = blockIdx.x * blockDim.x + tid;
    if (idx >= TOTAL) return;

    int l = idx / NCOL;
    int n = idx - l * NCOL;
    int t = n / N_THETA;
    int a = n - t * N_THETA;

    float a1 = vp[l * N_TRACES + t],  a2 = vp[(l + 1) * N_TRACES + t];
    float b1 = vs[l * N_TRACES + t],  b2 = vs[(l + 1) * N_TRACES + t];
    float r1 = rho[l * N_TRACES + t], r2 = rho[(l + 1) * N_TRACES + t];

    float sth = s_sth[a], cth = s_cth[a];
    float p = __fdividef(sth, a1);

    float st2 = fminf(fmaxf(p * a2, -1.f), 1.f);
    float ct2 = sqrtf(fmaxf(1.f - st2 * st2, 0.f));
    float sp1 = fminf(fmaxf(p * b1, -1.f), 1.f);
    float cp1 = sqrtf(fmaxf(1.f - sp1 * sp1, 0.f));
    float sp2 = fminf(fmaxf(p * b2, -1.f), 1.f);
    float cp2 = sqrtf(fmaxf(1.f - sp2 * sp2, 0.f));

    float rb1 = r1 * b1, rb2 = r2 * b2;
    float w1 = 1.f - 2.f * sp1 * sp1;
    float w2 = 1.f - 2.f * sp2 * sp2;

    float m00 = -sth,                  m01 = -cp1,                  m02 = st2,                   m03 = cp2;
    float m10 =  cth,                  m11 = -sp1,                  m12 = ct2,                   m13 = -sp2;
    float m20 = 2.f * rb1 * sp1 * cth, m21 = rb1 * w1,              m22 = 2.f * rb2 * sp2 * ct2, m23 = rb2 * w2;
    float m30 = -r1 * a1 * w1,         m31 = 2.f * rb1 * sp1 * cp1, m32 = r2 * a2 * w2,          m33 = -2.f * rb2 * sp2 * cp2;

    float n0 = sth, n1 = cth, n2 = m20, n3 = -m30;

    float P01 = m00 * m11 - m01 * m10;
    float P02 = m00 * m12 - m02 * m10;
    float P03 = m00 * m13 - m03 * m10;
    float P12 = m01 * m12 - m02 * m11;
    float P13 = m01 * m13 - m03 * m11;
    float P23 = m02 * m13 - m03 * m12;

    float Q01 = m20 * m31 - m21 * m30;
    float Q02 = m20 * m32 - m22 * m30;
    float Q03 = m20 * m33 - m23 * m30;
    float Q12 = m21 * m32 - m22 * m31;
    float Q13 = m21 * m33 - m23 * m31;
    float Q23 = m22 * m33 - m23 * m32;

    float detM = P01 * Q23 - P02 * Q13 + P03 * Q12
               + P12 * Q03 - P13 * Q02 + P23 * Q01;

    float Pn01 = n0 * m11 - m01 * n1;
    float Pn02 = n0 * m12 - m02 * n1;
    float Pn03 = n0 * m13 - m03 * n1;
    float Qn01 = n2 * m31 - m21 * n3;
    float Qn02 = n2 * m32 - m22 * n3;
    float Qn03 = n2 * m33 - m23 * n3;

    float detM0 = Pn01 * Q23 - Pn02 * Q13 + Pn03 * Q12
                + P12 * Qn03 - P13 * Qn02 + P23 * Qn01;

    float r = __fdividef(detM0, detM);
    __nv_bfloat16 hi = __float2bfloat16(r);
    float lof = r - __bfloat162float(hi);
    g_Rhi[l * NP + n] = hi;
    g_Rlo[l * NP + n] = __float2bfloat16(lof);
}

// ---------------------------------------------------------------------------
// W split: W[l, k] (250x250 f32) -> 256x256 bf16 hi/lo planes (zero padded)
// ---------------------------------------------------------------------------
__global__ void zoe_wsplit(const float* __restrict__ W) {
    int idx = blockIdx.x * blockDim.x + threadIdx.x;
    if (idx >= 256 * 256) return;
    int r = idx >> 8, k = idx & 255;
    float v = (r < L_LAYERS && k < L_LAYERS) ? W[r * L_LAYERS + k] : 0.f;
    __nv_bfloat16 hi = __float2bfloat16(v);
    float lof = v - __bfloat162float(hi);
    g_Whi[idx] = hi;
    g_Wlo[idx] = __float2bfloat16(lof);
}

// Re-zero R plane pad regions every launch (determinism insurance).
__global__ void zoe_zeropad() {
    int idx = blockIdx.x * blockDim.x + threadIdx.x;
    const int ROWPAD = (KPAD - NI) * NP;            // rows 249..255, all cols
    if (idx < ROWPAD) {
        int o = (NI * NP) + idx;
        g_Rhi[o] = __float2bfloat16(0.f);
        g_Rlo[o] = __float2bfloat16(0.f);
        return;
    }
    idx -= ROWPAD;
    const int COLPAD = NI * (NP - NCOL);            // rows 0..248, cols 18000..18047
    if (idx < COLPAD) {
        int r = idx / (NP - NCOL);
        int c = NCOL + idx - r * (NP - NCOL);
        g_Rhi[r * NP + c] = __float2bfloat16(0.f);
        g_Rlo[r * NP + c] = __float2bfloat16(0.f);
    }
}

// ---------------------------------------------------------------------------
// Phase 2: out[t, l, a] = sum_k W[l, k] * R[k, n], n = t*30 + a
// Split-bf16 HMMA GEMM: M=256(pad of 250), N=18000, K=256(pad of 249).
// Block 128x128, 8 warps (2x4), warp 64x32, m16n8k16 mma.
// acc += Ah*Bh + Ah*Bl + Al*Bh   (fp32 accumulate)
// cp.async double-buffered smem, ldmatrix fragment loads.
// ---------------------------------------------------------------------------
#define APITCH 24    // bf16 elems per A smem row (16 data + pad) -> 48B
#define BPITCH 136   // bf16 elems per B smem row (128 data + pad) -> 272B

__device__ __forceinline__ uint32_t smaddr(const void* p) {
    return (uint32_t)__cvta_generic_to_shared(p);
}
__device__ __forceinline__ void ldsm4(uint32_t a[4], uint32_t addr) {
    asm volatile("ldmatrix.sync.aligned.m8n8.x4.shared.b16 {%0,%1,%2,%3}, [%4];"
                 : "=r"(a[0]), "=r"(a[1]), "=r"(a[2]), "=r"(a[3]) : "r"(addr));
}
__device__ __forceinline__ void ldsm4t(uint32_t a[4], uint32_t addr) {
    asm volatile("ldmatrix.sync.aligned.m8n8.x4.trans.shared.b16 {%0,%1,%2,%3}, [%4];"
                 : "=r"(a[0]), "=r"(a[1]), "=r"(a[2]), "=r"(a[3]) : "r"(addr));
}
__device__ __forceinline__ void mma16816(float c[4], const uint32_t a[4], const uint32_t b[2]) {
    asm volatile("mma.sync.aligned.m16n8k16.row.col.f32.bf16.bf16.f32 "
                 "{%0,%1,%2,%3}, {%4,%5,%6,%7}, {%8,%9}, {%0,%1,%2,%3};"
                 : "+f"(c[0]), "+f"(c[1]), "+f"(c[2]), "+f"(c[3])
                 : "r"(a[0]), "r"(a[1]), "r"(a[2]), "r"(a[3]), "r"(b[0]), "r"(b[1]));
}
#define CP16(dst, src) \
    asm volatile("cp.async.ca.shared.global [%0], [%1], 16;" :: "r"(dst), "l"(src))
#define CP_COMMIT() asm volatile("cp.async.commit_group;")
#define CP_WAIT(n)  asm volatile("cp.async.wait_group %0;" :: "n"(n))

__global__ __launch_bounds__(256, 2)
void zoe_gemm(float* __restrict__ out) {
    __shared__ __nv_bfloat16 Ah[2][128][APITCH];
    __shared__ __nv_bfloat16 Al[2][128][APITCH];
    __shared__ __nv_bfloat16 Bh[2][16][BPITCH];
    __shared__ __nv_bfloat16 Bl[2][16][BPITCH];

    int tid = threadIdx.x;
    int bm = blockIdx.y * 128;
    int bn = blockIdx.x * 128;

    // fill mappings (256 threads)
    int ar = tid >> 1;            // A row 0..127
    int ac = (tid & 1) * 8;       // A k-offset 0 or 8 within the 16-chunk
    int br = tid >> 4;            // B k-row 0..15
    int bc = (tid & 15) * 8;      // B n-offset 0..120

    const __nv_bfloat16* pWhi = &g_Whi[(bm + ar) * 256 + ac];
    const __nv_bfloat16* pWlo = &g_Wlo[(bm + ar) * 256 + ac];
    const __nv_bfloat16* pRhi = &g_Rhi[(size_t)br * NP + bn + bc];
    const __nv_bfloat16* pRlo = &g_Rlo[(size_t)br * NP + bn + bc];

    // warp tiling
    int wid = tid >> 5, lane = tid & 31;
    int wm = (wid >> 2) * 64;     // 0 or 64
    int wn = (wid & 3) * 32;      // 0,32,64,96
    int r8 = lane >> 3, i8 = lane & 7;
    int a_row = wm + (r8 & 1) * 8 + i8;        // + mt*16
    int a_col = (r8 >> 1) * 8;
    int b_krow = (r8 & 1) * 8 + i8;
    int b_ncol = wn + (r8 >> 1) * 8;           // + pair*16

    float acc[4][4][4];
#pragma unroll
    for (int mt = 0; mt < 4; mt++)
#pragma unroll
        for (int nt = 0; nt < 4; nt++)
#pragma unroll
            for (int e = 0; e < 4; e++) acc[mt][nt][e] = 0.f;

    // prologue: stage 0
    {
        CP16(smaddr(&Ah[0][ar][ac]), pWhi);
        CP16(smaddr(&Al[0][ar][ac]), pWlo);
        CP16(smaddr(&Bh[0][br][bc]), pRhi);
        CP16(smaddr(&Bl[0][br][bc]), pRlo);
        CP_COMMIT();
    }

    const int NSTEP = KPAD / 16;  // 16
    for (int s = 0; s < NSTEP; s++) {
        int buf = s & 1;
        if (s + 1 < NSTEP) {
            int k0 = (s + 1) * 16;
            int nb = buf ^ 1;
            CP16(smaddr(&Ah[nb][ar][ac]), pWhi + k0);
            CP16(smaddr(&Al[nb][ar][ac]), pWlo + k0);
            CP16(smaddr(&Bh[nb][br][bc]), pRhi + (size_t)k0 * NP);
            CP16(smaddr(&Bl[nb][br][bc]), pRlo + (size_t)k0 * NP);
            CP_COMMIT();
            CP_WAIT(1);
        } else {
            CP_WAIT(0);
        }
        __syncthreads();

        // B fragments: 4 n-tiles, hi+lo
        uint32_t bh[4][2], bl[4][2];
#pragma unroll
        for (int pair = 0; pair < 2; pair++) {
            uint32_t t4[4];
            ldsm4t(t4, smaddr(&Bh[buf][b_krow][b_ncol + pair * 16]));
            bh[pair * 2][0] = t4[0]; bh[pair * 2][1] = t4[1];
            bh[pair * 2 + 1][0] = t4[2]; bh[pair * 2 + 1][1] = t4[3];
            ldsm4t(t4, smaddr(&Bl[buf][b_krow][b_ncol + pair * 16]));
            bl[pair * 2][0] = t4[0]; bl[pair * 2][1] = t4[1];
            bl[pair * 2 + 1][0] = t4[2]; bl[pair * 2 + 1][1] = t4[3];
        }

#pragma unroll
        for (int mt = 0; mt < 4; mt++) {
            uint32_t ah[4], al4[4];
            ldsm4(ah,  smaddr(&Ah[buf][a_row + mt * 16][a_col]));
            ldsm4(al4, smaddr(&Al[buf][a_row + mt * 16][a_col]));
#pragma unroll
            for (int nt = 0; nt < 4; nt++) {
                mma16816(acc[mt][nt], ah,  bh[nt]);   // hi*hi
                mma16816(acc[mt][nt], ah,  bl[nt]);   // hi*lo
                mma16816(acc[mt][nt], al4, bh[nt]);   // lo*hi
            }
        }
        __syncthreads();   // release buf for fill of stage s+2
    }

    // epilogue: D fragment: d0=(l0,n0) d1=(l0,n0+1) d2=(l0+8,n0) d3=(l0+8,n0+1)
#pragma unroll
    for (int mt = 0; mt < 4; mt++) {
#pragma unroll
        for (int nt = 0; nt < 4; nt++) {
            int l0 = bm + wm + mt * 16 + (lane >> 2);
            int n0 = bn + wn + nt * 8 + (lane & 3) * 2;
#pragma unroll
            for (int e = 0; e < 4; e++) {
                int l = l0 + (e >> 1) * 8;
                int n = n0 + (e & 1);
                if (l < L_LAYERS && n < NCOL) {
                    int t = n / N_THETA;
                    int a = n - t * N_THETA;
                    out[t * (L_LAYERS * N_THETA) + l * N_THETA + a] = acc[mt][nt][e];
                }
            }
        }
    }
}

extern "C" void kernel_launch(void* const* d_in, const int* in_sizes, int n_in,
                              void* d_out, int out_size) {
    const float* vp      = (const float*)d_in[0];
    const float* vs      = (const float*)d_in[1];
    const float* rho     = (const float*)d_in[2];
    const float* theta   = (const float*)d_in[3];
    const float* wavemat = (const float*)d_in[4];
    float* out = (float*)d_out;

    zoe_wsplit<<<(256 * 256 + 255) / 256, 256>>>(wavemat);
    {
        int padtot = (KPAD - NI) * NP + NI * (NP - NCOL);
        zoe_zeropad<<<(padtot + 255) / 256, 256>>>();
    }
    zoe_phase1<<<(TOTAL + 255) / 256, 256>>>(vp, vs, rho, theta);

    dim3 grid((NCOL + 127) / 128, 2);
    zoe_gemm<<<grid, 256>>>(out);
}